// round 9
// baseline (speedup 1.0000x reference)
#include <cuda_runtime.h>
#include <stdint.h>
#include <math.h>

// Sizes (fixed for this problem)
#define BB 16
#define LL 128
#define HH 256
#define DD 256
#define BL (BB*LL)              // 2048
#define NEL (BB*LL*LL)          // 262144
#define OFF_MS 0
#define OFF_S  NEL              // 262144
#define OFF_E  (2*NEL)          // 524288
#define OFF_GB (3*NEL)          // 786432
#define OFF_LSM (3*NEL + LL*LL) // 802816
#define OFF_ER (OFF_LSM + 1)    // 802817

// Scratch (no cudaMalloc allowed). g_el/g_er hold exp(2*dot).
__device__ float g_el[BL*DD];
__device__ float g_er[BL*DD];
__device__ float g_ent_part[256];
__device__ float g_lsm_part[256];
__device__ int   g_cnt[LL*LL];   // zero at load; tail kernel resets each call

#define TWO_LOG2E 2.8853900817779268f   // 2*log2(e)

__device__ __forceinline__ float ex2f(float x) {
    float e; asm("ex2.approx.f32 %0, %1;" : "=f"(e) : "f"(x)); return e;
}
__device__ __forceinline__ float rcpf(float x) {
    float r; asm("rcp.approx.f32 %0, %1;" : "=f"(r) : "f"(x)); return r;
}

// ---------------------------------------------------------------------------
// 4xTF32 split helpers (fp32-equivalent accuracy on tensor pipe)
// ---------------------------------------------------------------------------
__device__ __forceinline__ void tf32_split(float x, uint32_t& hi, uint32_t& lo) {
    asm("cvt.rna.tf32.f32 %0, %1;" : "=r"(hi) : "f"(x));
    float l = x - __uint_as_float(hi);
    asm("cvt.rna.tf32.f32 %0, %1;" : "=r"(lo) : "f"(l));
}

__device__ __forceinline__ void mma_tf32(float* c, const uint32_t* a,
                                         const uint32_t* b) {
    asm volatile(
        "mma.sync.aligned.m16n8k8.row.col.f32.tf32.tf32.f32 "
        "{%0,%1,%2,%3}, {%4,%5,%6,%7}, {%8,%9}, {%0,%1,%2,%3};"
        : "+f"(c[0]), "+f"(c[1]), "+f"(c[2]), "+f"(c[3])
        : "r"(a[0]), "r"(a[1]), "r"(a[2]), "r"(a[3]), "r"(b[0]), "r"(b[1]));
}

// ---------------------------------------------------------------------------
// GEMM (tensor core): C = exp(2 * (A(2048x256) @ W(256x256))), 4xTF32 split.
// Block 256 thr (8 warps), tile 64m x 64n, warp tile 32m x 16n
// (2 m-frags x 2 n-frags of m16n8k8). k staged 32/stage, 8 stages.
// As[64][36] (bank-exact a-frag reads), Bs[32][72] (bank-exact b-frag reads).
// grid (4, 32, 2) = 256 blocks.
// ---------------------------------------------------------------------------
#define GA_STR 36
#define GB_STR 72

__global__ __launch_bounds__(256, 2)
void gemm_tc_kernel(const float* __restrict__ A,
                    const float* __restrict__ Wl,
                    const float* __restrict__ Wr) {
    const float* W = blockIdx.z ? Wr : Wl;
    float* C = blockIdx.z ? g_er : g_el;
    __shared__ __align__(16) float As[64 * GA_STR];
    __shared__ __align__(16) float Bs[32 * GB_STR];
    const int tid = threadIdx.x;
    const int w = tid >> 5, lane = tid & 31;
    const int m0 = blockIdx.y * 64, n0 = blockIdx.x * 64;
    const int wm = (w & 1) * 32, wn = (w >> 1) * 16;

    // global load mapping (per stage: A 64x32, W 32x64; 2 float4 each)
    const int arow = tid >> 3, acol = (tid & 7) * 4;
    const int brow = tid >> 4, bcol = (tid & 15) * 4;
    const float* Ap = A + (m0 + arow) * 256 + acol;
    const float* Wp = W + brow * 256 + n0 + bcol;

    float4 ra0 = *(const float4*)(Ap);
    float4 ra1 = *(const float4*)(Ap + 32 * 256);
    float4 rb0 = *(const float4*)(Wp);
    float4 rb1 = *(const float4*)(Wp + 16 * 256);

    float acc[2][2][4];
#pragma unroll
    for (int mi = 0; mi < 2; mi++)
#pragma unroll
        for (int ni = 0; ni < 2; ni++)
#pragma unroll
            for (int q = 0; q < 4; q++) acc[mi][ni][q] = 0.0f;

    const int r = lane >> 2, cq = lane & 3;

    for (int s = 0; s < 8; s++) {
        *(float4*)&As[arow * GA_STR + acol]        = ra0;
        *(float4*)&As[(arow + 32) * GA_STR + acol] = ra1;
        *(float4*)&Bs[brow * GB_STR + bcol]        = rb0;
        *(float4*)&Bs[(brow + 16) * GB_STR + bcol] = rb1;
        __syncthreads();
        if (s < 7) {
            ra0 = *(const float4*)(Ap + (s + 1) * 32);
            ra1 = *(const float4*)(Ap + (s + 1) * 32 + 32 * 256);
            rb0 = *(const float4*)(Wp + (s + 1) * 32 * 256);
            rb1 = *(const float4*)(Wp + (s + 1) * 32 * 256 + 16 * 256);
        }
#pragma unroll
        for (int k8 = 0; k8 < 32; k8 += 8) {
            uint32_t ahi[2][4], alo[2][4];
#pragma unroll
            for (int mi = 0; mi < 2; mi++) {
                const float* ab = &As[(wm + mi * 16 + r) * GA_STR + k8 + cq];
                tf32_split(ab[0],              ahi[mi][0], alo[mi][0]);
                tf32_split(ab[8 * GA_STR],     ahi[mi][1], alo[mi][1]);
                tf32_split(ab[4],              ahi[mi][2], alo[mi][2]);
                tf32_split(ab[8 * GA_STR + 4], ahi[mi][3], alo[mi][3]);
            }
            uint32_t bhi[2][2], blo[2][2];
#pragma unroll
            for (int ni = 0; ni < 2; ni++) {
                const float* bb = &Bs[(k8 + cq) * GB_STR + wn + ni * 8 + r];
                tf32_split(bb[0],          bhi[ni][0], blo[ni][0]);
                tf32_split(bb[4 * GB_STR], bhi[ni][1], blo[ni][1]);
            }
#pragma unroll
            for (int mi = 0; mi < 2; mi++)
#pragma unroll
                for (int ni = 0; ni < 2; ni++) {
                    mma_tf32(acc[mi][ni], alo[mi], blo[ni]);
                    mma_tf32(acc[mi][ni], alo[mi], bhi[ni]);
                    mma_tf32(acc[mi][ni], ahi[mi], blo[ni]);
                    mma_tf32(acc[mi][ni], ahi[mi], bhi[ni]);
                }
        }
        __syncthreads();
    }

    // epilogue: ex2(2*log2e * dot), fragment rows r/r+8, cols 2cq/2cq+1
#pragma unroll
    for (int mi = 0; mi < 2; mi++)
#pragma unroll
        for (int ni = 0; ni < 2; ni++) {
            int row = m0 + wm + mi * 16 + r;
            int col = n0 + wn + ni * 8 + 2 * cq;
            float2 lo2, hi2;
            lo2.x = ex2f(acc[mi][ni][0] * TWO_LOG2E);
            lo2.y = ex2f(acc[mi][ni][1] * TWO_LOG2E);
            hi2.x = ex2f(acc[mi][ni][2] * TWO_LOG2E);
            hi2.y = ex2f(acc[mi][ni][3] * TWO_LOG2E);
            *(float2*)&C[row * 256 + col]       = lo2;
            *(float2*)&C[(row + 8) * 256 + col] = hi2;
        }
}

// ---------------------------------------------------------------------------
// Threefry-2x32, key = (0,1) [jax.random.key(1)], partitionable bits.
// ---------------------------------------------------------------------------
__device__ __forceinline__ uint32_t rotl32(uint32_t v, int r) {
    return __funnelshift_l(v, v, r);
}
__device__ __forceinline__ uint32_t threefry_bits(uint32_t idx) {
    const uint32_t K0 = 0u, K1 = 1u, K2 = 0x1BD11BDBu;
    uint32_t x0 = K0;
    uint32_t x1 = idx + K1;
#define TF_ROUND(r) { x0 += x1; x1 = rotl32(x1, (r)); x1 ^= x0; }
    TF_ROUND(13) TF_ROUND(15) TF_ROUND(26) TF_ROUND(6)
    x0 += K1; x1 += K2 + 1u;
    TF_ROUND(17) TF_ROUND(29) TF_ROUND(16) TF_ROUND(24)
    x0 += K2; x1 += K0 + 2u;
    TF_ROUND(13) TF_ROUND(15) TF_ROUND(26) TF_ROUND(6)
    x0 += K0; x1 += K1 + 3u;
    TF_ROUND(17) TF_ROUND(29) TF_ROUND(16) TF_ROUND(24)
    x0 += K1; x1 += K2 + 4u;
    TF_ROUND(13) TF_ROUND(15) TF_ROUND(26) TF_ROUND(6)
    x0 += K2; x1 += K0 + 5u;
#undef TF_ROUND
    return x0 ^ x1;
}

// Epilogue for one (b,i,j): writes ms/sample/entropy, counts sample into
// g_cnt (integer atomic -> deterministic), returns (entropy, lsm_term).
__device__ __forceinline__ float2 epi_one(int b, int i, int j, float logit,
                                          float* __restrict__ out) {
    float ms = (i == j) ? (logit - 1e8f) : logit;
    uint32_t f = ((uint32_t)b << 14) | ((uint32_t)i << 7) | (uint32_t)j;
    uint32_t bits = threefry_bits(f);
    float u = __uint_as_float((bits >> 9) | 0x3f800000u) - 1.0f;
    float p = 1.0f / (1.0f + expf(-ms));
    float c = log1pf(expf(-fabsf(ms)));          // shared softplus tail
    float sp_pos = fmaxf(ms, 0.0f) + c;          // softplus(ms)
    float sp_neg = fmaxf(-ms, 0.0f) + c;         // softplus(-ms)
    float ent = fmaf(p, sp_neg, (1.0f - p) * sp_pos);
    float s;
    if (u < p) { s = 1.0f; atomicAdd(&g_cnt[i * LL + j], 1); } else s = 0.0f;
    out[OFF_MS + f] = ms;
    out[OFF_S + f]  = s;
    out[OFF_E + f]  = ent;
    float lsm = sp_pos - ms * s;
    return make_float2(ent, lsm);
}

// ---------------------------------------------------------------------------
// Pairwise core. tanh(l+r) = 1 - 2/(1 + el*er); logit = -2*sum U*(r-0.5) + bias.
// grid (4, 4, 16): 32x32 tiles, 128 threads, 2x4 microtile
// (i: ty, ty+16; j: tx, tx+8, tx+16, tx+24), d-chunks of 128 in smem.
// LDS traffic 3.5 B/element-d -> MUFU (rcp) is the only binding pipe.
// ---------------------------------------------------------------------------
#define PW_STR 132

__device__ __forceinline__ void pw_mac(float l0, float l1, float r0, float r1,
                                       float r2, float r3, float u,
                                       float acc[2][4]) {
    acc[0][0] = fmaf(u, rcpf(fmaf(l0, r0, 1.0f)) - 0.5f, acc[0][0]);
    acc[0][1] = fmaf(u, rcpf(fmaf(l0, r1, 1.0f)) - 0.5f, acc[0][1]);
    acc[0][2] = fmaf(u, rcpf(fmaf(l0, r2, 1.0f)) - 0.5f, acc[0][2]);
    acc[0][3] = fmaf(u, rcpf(fmaf(l0, r3, 1.0f)) - 0.5f, acc[0][3]);
    acc[1][0] = fmaf(u, rcpf(fmaf(l1, r0, 1.0f)) - 0.5f, acc[1][0]);
    acc[1][1] = fmaf(u, rcpf(fmaf(l1, r1, 1.0f)) - 0.5f, acc[1][1]);
    acc[1][2] = fmaf(u, rcpf(fmaf(l1, r2, 1.0f)) - 0.5f, acc[1][2]);
    acc[1][3] = fmaf(u, rcpf(fmaf(l1, r3, 1.0f)) - 0.5f, acc[1][3]);
}

__global__ __launch_bounds__(128, 4)
void pairwise_kernel(const float* __restrict__ Uv,
                     const float* __restrict__ biasp,
                     float* __restrict__ out) {
    __shared__ __align__(16) float sl[32 * PW_STR];
    __shared__ __align__(16) float sr[32 * PW_STR];
    __shared__ __align__(16) float su[256];
    __shared__ float rshare[2][4];
    const int tid = threadIdx.x;
    const int tx = tid & 7, ty = tid >> 3;        // j-base, i-base
    const int b = blockIdx.z;
    const int ibase = blockIdx.y * 32, jbase = blockIdx.x * 32;

    su[tid] = Uv[tid];
    su[tid + 128] = Uv[tid + 128];

    float acc[2][4];
#pragma unroll
    for (int u = 0; u < 2; u++)
#pragma unroll
        for (int v = 0; v < 4; v++) acc[u][v] = 0.0f;

    for (int k0 = 0; k0 < 256; k0 += 128) {
        __syncthreads();
        // load 32 l-rows + 32 r-rows x 128 floats (32 float4 per row)
        for (int idx = tid; idx < 64 * 32; idx += 128) {
            int rr = idx >> 5, cc = (idx & 31) << 2;
            if (rr < 32) {
                *(float4*)&sl[rr * PW_STR + cc] =
                    *(const float4*)&g_el[(b * 128 + ibase + rr) * 256 + k0 + cc];
            } else {
                *(float4*)&sr[(rr - 32) * PW_STR + cc] =
                    *(const float4*)&g_er[(b * 128 + jbase + (rr - 32)) * 256 + k0 + cc];
            }
        }
        __syncthreads();
        const float* pl0 = sl + ty * PW_STR;
        const float* pl1 = sl + (ty + 16) * PW_STR;
        const float* pr0 = sr + tx * PW_STR;
        const float* pr1 = sr + (tx + 8) * PW_STR;
        const float* pr2 = sr + (tx + 16) * PW_STR;
        const float* pr3 = sr + (tx + 24) * PW_STR;
        const float* pu  = su + k0;
#pragma unroll 2
        for (int d = 0; d < 128; d += 4) {
            float4 L0 = *(const float4*)(pl0 + d);
            float4 L1 = *(const float4*)(pl1 + d);
            float4 R0 = *(const float4*)(pr0 + d);
            float4 R1 = *(const float4*)(pr1 + d);
            float4 R2 = *(const float4*)(pr2 + d);
            float4 R3 = *(const float4*)(pr3 + d);
            float4 U  = *(const float4*)(pu + d);
            pw_mac(L0.x, L1.x, R0.x, R1.x, R2.x, R3.x, U.x, acc);
            pw_mac(L0.y, L1.y, R0.y, R1.y, R2.y, R3.y, U.y, acc);
            pw_mac(L0.z, L1.z, R0.z, R1.z, R2.z, R3.z, U.z, acc);
            pw_mac(L0.w, L1.w, R0.w, R1.w, R2.w, R3.w, U.w, acc);
        }
    }

    const float bias = __ldg(biasp);
    float ent = 0.0f, lsm = 0.0f;
#pragma unroll
    for (int u = 0; u < 2; u++)
#pragma unroll
        for (int v = 0; v < 4; v++) {
            float2 e = epi_one(b, ibase + ty + 16 * u, jbase + tx + 8 * v,
                               fmaf(-2.0f, acc[u][v], bias), out);
            ent += e.x; lsm += e.y;
        }

    // block reduce (shfl tree + 4-warp combine), deterministic
#pragma unroll
    for (int o = 16; o > 0; o >>= 1) {
        ent += __shfl_xor_sync(0xffffffffu, ent, o);
        lsm += __shfl_xor_sync(0xffffffffu, lsm, o);
    }
    const int wid = tid >> 5;
    if ((tid & 31) == 0) { rshare[0][wid] = ent; rshare[1][wid] = lsm; }
    __syncthreads();
    if (tid == 0) {
        float se = 0.0f, sm = 0.0f;
#pragma unroll
        for (int ww = 0; ww < 4; ww++) { se += rshare[0][ww]; sm += rshare[1][ww]; }
        const int bid = (b * 4 + blockIdx.y) * 4 + blockIdx.x; // 0..255
        g_ent_part[bid] = se;
        g_lsm_part[bid] = sm;
    }
}

// ---------------------------------------------------------------------------
// Tail: blocks 0-63 convert+reset graph_batch counts; block 64 finishes
// entropy_regularization (16 per-batch sums of 16 partials, fixed order)
// and the log_softmax scalar (one warp reduces 256 partials).
// ---------------------------------------------------------------------------
__global__ void tail_kernel(float* __restrict__ out) {
    const int bidx = blockIdx.x;
    if (bidx < 64) {
        int idx = bidx * 256 + threadIdx.x;   // 0..16383
        out[OFF_GB + idx] = (float)g_cnt[idx] * 0.0625f;
        g_cnt[idx] = 0;                        // reset for next graph replay
    } else {
        int t = threadIdx.x;
        if (t < 16) {
            float s = 0.0f;
#pragma unroll
            for (int k = 0; k < 16; k++) s += g_ent_part[t * 16 + k];
            out[OFF_ER + t] = s * (1.0f / 16384.0f);
        }
        if (t >= 32 && t < 64) {
            int lane = t - 32;
            float s = 0.0f;
#pragma unroll
            for (int k = 0; k < 8; k++) s += g_lsm_part[lane * 8 + k];
#pragma unroll
            for (int o = 16; o > 0; o >>= 1)
                s += __shfl_xor_sync(0xffffffffu, s, o);
            if (lane == 0) out[OFF_LSM] = s * (1.0f / (float)NEL);
        }
    }
}

// ---------------------------------------------------------------------------
extern "C" void kernel_launch(void* const* d_in, const int* in_sizes, int n_in,
                              void* d_out, int out_size) {
    (void)in_sizes; (void)n_in; (void)out_size;
    const float* enc  = (const float*)d_in[0]; // (16,128,256)
    const float* W_l  = (const float*)d_in[1]; // (256,256)
    const float* W_r  = (const float*)d_in[2]; // (256,256)
    const float* U    = (const float*)d_in[3]; // (256,)
    const float* bias = (const float*)d_in[4]; // (1,)
    float* out = (float*)d_out;

    gemm_tc_kernel<<<dim3(4, 32, 2), 256>>>(enc, W_l, W_r);
    pairwise_kernel<<<dim3(4, 4, 16), 128>>>(U, bias, out);
    tail_kernel<<<65, 256>>>(out);
}

// round 11
// speedup vs baseline: 1.0047x; 1.0047x over previous
#include <cuda_runtime.h>
#include <stdint.h>
#include <math.h>

// Sizes (fixed for this problem)
#define BB 16
#define LL 128
#define HH 256
#define DD 256
#define BL (BB*LL)              // 2048
#define NEL (BB*LL*LL)          // 262144
#define OFF_MS 0
#define OFF_S  NEL              // 262144
#define OFF_E  (2*NEL)          // 524288
#define OFF_GB (3*NEL)          // 786432
#define OFF_LSM (3*NEL + LL*LL) // 802816
#define OFF_ER (OFF_LSM + 1)    // 802817

// Scratch (no cudaMalloc allowed).
__device__ float g_el[BL*DD];        // exp(2*dot_l)
__device__ float g_er[BL*DD];        // exp(2*dot_r)
__device__ float g_ahi[BL*DD];       // tf32 split of encoder_output
__device__ float g_alo[BL*DD];
__device__ float g_whi[2][HH*DD];    // tf32 split of W_l / W_r
__device__ float g_wlo[2][HH*DD];
__device__ float g_ent_part[1024];
__device__ float g_lsm_part[1024];
__device__ int   g_cnt[LL*LL];       // zero at load; tail resets each call

#define TWO_LOG2E 2.8853900817779268f   // 2*log2(e)

__device__ __forceinline__ float ex2f(float x) {
    float e; asm("ex2.approx.f32 %0, %1;" : "=f"(e) : "f"(x)); return e;
}
__device__ __forceinline__ float rcpf(float x) {
    float r; asm("rcp.approx.f32 %0, %1;" : "=f"(r) : "f"(x)); return r;
}

// ---------------------------------------------------------------------------
// 4xTF32 split helpers (fp32-equivalent accuracy on tensor pipe)
// ---------------------------------------------------------------------------
__device__ __forceinline__ void tf32_split(float x, uint32_t& hi, uint32_t& lo) {
    asm("cvt.rna.tf32.f32 %0, %1;" : "=r"(hi) : "f"(x));
    float l = x - __uint_as_float(hi);
    asm("cvt.rna.tf32.f32 %0, %1;" : "=r"(lo) : "f"(l));
}

__device__ __forceinline__ void split4(float4 v, float4& h, float4& l) {
    uint32_t hh, ll;
    tf32_split(v.x, hh, ll); h.x = __uint_as_float(hh); l.x = __uint_as_float(ll);
    tf32_split(v.y, hh, ll); h.y = __uint_as_float(hh); l.y = __uint_as_float(ll);
    tf32_split(v.z, hh, ll); h.z = __uint_as_float(hh); l.z = __uint_as_float(ll);
    tf32_split(v.w, hh, ll); h.w = __uint_as_float(hh); l.w = __uint_as_float(ll);
}

__device__ __forceinline__ void mma_tf32(float* c, const uint32_t* a,
                                         const uint32_t* b) {
    asm volatile(
        "mma.sync.aligned.m16n8k8.row.col.f32.tf32.tf32.f32 "
        "{%0,%1,%2,%3}, {%4,%5,%6,%7}, {%8,%9}, {%0,%1,%2,%3};"
        : "+f"(c[0]), "+f"(c[1]), "+f"(c[2]), "+f"(c[3])
        : "r"(a[0]), "r"(a[1]), "r"(a[2]), "r"(a[3]), "r"(b[0]), "r"(b[1]));
}

// ---------------------------------------------------------------------------
// Split kernel: precompute hi/lo tf32 decomposition of A and both W matrices.
// A: 131072 float4; W: 2 x 16384 float4. grid 640 x 256.
// ---------------------------------------------------------------------------
__global__ void split_kernel(const float* __restrict__ A,
                             const float* __restrict__ Wl,
                             const float* __restrict__ Wr) {
    int idx = blockIdx.x * 256 + threadIdx.x;
    if (idx < 131072) {
        float4 v = ((const float4*)A)[idx];
        float4 h, l;
        split4(v, h, l);
        ((float4*)g_ahi)[idx] = h;
        ((float4*)g_alo)[idx] = l;
    } else {
        int k = idx - 131072;          // 0..32767
        int sel = k >> 14;             // 0: Wl, 1: Wr
        int off = k & 16383;
        float4 v = ((const float4*)(sel ? Wr : Wl))[off];
        float4 h, l;
        split4(v, h, l);
        ((float4*)g_whi[sel])[off] = h;
        ((float4*)g_wlo[sel])[off] = l;
    }
}

// ---------------------------------------------------------------------------
// GEMM (tensor core): C = exp(2 * (A @ W)), pre-split 4xTF32, pure LDS+MMA.
// Block 256 thr (8 warps), tile 64m x 64n, warp tile 32m x 16n.
// k staged 32/stage, 8 stages; hi/lo staged in separate smem arrays.
// grid (4, 32, 2) = 256 blocks.
// ---------------------------------------------------------------------------
#define GA_STR 36
#define GB_STR 72

__global__ __launch_bounds__(256, 2)
void gemm_tc_kernel() {
    const float* Ah = g_ahi;
    const float* Al = g_alo;
    const float* Wh = g_whi[blockIdx.z];
    const float* Wlo = g_wlo[blockIdx.z];
    float* C = blockIdx.z ? g_er : g_el;
    __shared__ __align__(16) float Ash[64 * GA_STR];
    __shared__ __align__(16) float Asl[64 * GA_STR];
    __shared__ __align__(16) float Bsh[32 * GB_STR];
    __shared__ __align__(16) float Bsl[32 * GB_STR];
    const int tid = threadIdx.x;
    const int w = tid >> 5, lane = tid & 31;
    const int m0 = blockIdx.y * 64, n0 = blockIdx.x * 64;
    const int wm = (w & 1) * 32, wn = (w >> 1) * 16;

    const int arow = tid >> 3, acol = (tid & 7) * 4;   // A: 32 rows x 32 k x2
    const int brow = tid >> 4, bcol = (tid & 15) * 4;  // W: 16 rows x 64 n x2
    const int aoff = (m0 + arow) * 256 + acol;
    const int boff = brow * 256 + n0 + bcol;

    float4 rah0 = *(const float4*)(Ah + aoff);
    float4 rah1 = *(const float4*)(Ah + aoff + 32 * 256);
    float4 ral0 = *(const float4*)(Al + aoff);
    float4 ral1 = *(const float4*)(Al + aoff + 32 * 256);
    float4 rbh0 = *(const float4*)(Wh + boff);
    float4 rbh1 = *(const float4*)(Wh + boff + 16 * 256);
    float4 rbl0 = *(const float4*)(Wlo + boff);
    float4 rbl1 = *(const float4*)(Wlo + boff + 16 * 256);

    float acc[2][2][4];
#pragma unroll
    for (int mi = 0; mi < 2; mi++)
#pragma unroll
        for (int ni = 0; ni < 2; ni++)
#pragma unroll
            for (int q = 0; q < 4; q++) acc[mi][ni][q] = 0.0f;

    const int r = lane >> 2, cq = lane & 3;

    for (int s = 0; s < 8; s++) {
        *(float4*)&Ash[arow * GA_STR + acol]        = rah0;
        *(float4*)&Ash[(arow + 32) * GA_STR + acol] = rah1;
        *(float4*)&Asl[arow * GA_STR + acol]        = ral0;
        *(float4*)&Asl[(arow + 32) * GA_STR + acol] = ral1;
        *(float4*)&Bsh[brow * GB_STR + bcol]        = rbh0;
        *(float4*)&Bsh[(brow + 16) * GB_STR + bcol] = rbh1;
        *(float4*)&Bsl[brow * GB_STR + bcol]        = rbl0;
        *(float4*)&Bsl[(brow + 16) * GB_STR + bcol] = rbl1;
        __syncthreads();
        if (s < 7) {
            int as = aoff + (s + 1) * 32;
            int bs = boff + (s + 1) * 32 * 256;
            rah0 = *(const float4*)(Ah + as);
            rah1 = *(const float4*)(Ah + as + 32 * 256);
            ral0 = *(const float4*)(Al + as);
            ral1 = *(const float4*)(Al + as + 32 * 256);
            rbh0 = *(const float4*)(Wh + bs);
            rbh1 = *(const float4*)(Wh + bs + 16 * 256);
            rbl0 = *(const float4*)(Wlo + bs);
            rbl1 = *(const float4*)(Wlo + bs + 16 * 256);
        }
#pragma unroll
        for (int k8 = 0; k8 < 32; k8 += 8) {
            uint32_t ahi[2][4], alo[2][4];
#pragma unroll
            for (int mi = 0; mi < 2; mi++) {
                const int base = (wm + mi * 16 + r) * GA_STR + k8 + cq;
                ahi[mi][0] = __float_as_uint(Ash[base]);
                ahi[mi][1] = __float_as_uint(Ash[base + 8 * GA_STR]);
                ahi[mi][2] = __float_as_uint(Ash[base + 4]);
                ahi[mi][3] = __float_as_uint(Ash[base + 8 * GA_STR + 4]);
                alo[mi][0] = __float_as_uint(Asl[base]);
                alo[mi][1] = __float_as_uint(Asl[base + 8 * GA_STR]);
                alo[mi][2] = __float_as_uint(Asl[base + 4]);
                alo[mi][3] = __float_as_uint(Asl[base + 8 * GA_STR + 4]);
            }
            uint32_t bhi[2][2], blo[2][2];
#pragma unroll
            for (int ni = 0; ni < 2; ni++) {
                const int base = (k8 + cq) * GB_STR + wn + ni * 8 + r;
                bhi[ni][0] = __float_as_uint(Bsh[base]);
                bhi[ni][1] = __float_as_uint(Bsh[base + 4 * GB_STR]);
                blo[ni][0] = __float_as_uint(Bsl[base]);
                blo[ni][1] = __float_as_uint(Bsl[base + 4 * GB_STR]);
            }
#pragma unroll
            for (int mi = 0; mi < 2; mi++)
#pragma unroll
                for (int ni = 0; ni < 2; ni++) {
                    mma_tf32(acc[mi][ni], alo[mi], blo[ni]);
                    mma_tf32(acc[mi][ni], alo[mi], bhi[ni]);
                    mma_tf32(acc[mi][ni], ahi[mi], blo[ni]);
                    mma_tf32(acc[mi][ni], ahi[mi], bhi[ni]);
                }
        }
        __syncthreads();
    }

#pragma unroll
    for (int mi = 0; mi < 2; mi++)
#pragma unroll
        for (int ni = 0; ni < 2; ni++) {
            int row = m0 + wm + mi * 16 + r;
            int col = n0 + wn + ni * 8 + 2 * cq;
            float2 lo2, hi2;
            lo2.x = ex2f(acc[mi][ni][0] * TWO_LOG2E);
            lo2.y = ex2f(acc[mi][ni][1] * TWO_LOG2E);
            hi2.x = ex2f(acc[mi][ni][2] * TWO_LOG2E);
            hi2.y = ex2f(acc[mi][ni][3] * TWO_LOG2E);
            *(float2*)&C[row * 256 + col]       = lo2;
            *(float2*)&C[(row + 8) * 256 + col] = hi2;
        }
}

// ---------------------------------------------------------------------------
// Threefry-2x32, key = (0,1) [jax.random.key(1)], partitionable bits.
// ---------------------------------------------------------------------------
__device__ __forceinline__ uint32_t rotl32(uint32_t v, int r) {
    return __funnelshift_l(v, v, r);
}
__device__ __forceinline__ uint32_t threefry_bits(uint32_t idx) {
    const uint32_t K0 = 0u, K1 = 1u, K2 = 0x1BD11BDBu;
    uint32_t x0 = K0;
    uint32_t x1 = idx + K1;
#define TF_ROUND(r) { x0 += x1; x1 = rotl32(x1, (r)); x1 ^= x0; }
    TF_ROUND(13) TF_ROUND(15) TF_ROUND(26) TF_ROUND(6)
    x0 += K1; x1 += K2 + 1u;
    TF_ROUND(17) TF_ROUND(29) TF_ROUND(16) TF_ROUND(24)
    x0 += K2; x1 += K0 + 2u;
    TF_ROUND(13) TF_ROUND(15) TF_ROUND(26) TF_ROUND(6)
    x0 += K0; x1 += K1 + 3u;
    TF_ROUND(17) TF_ROUND(29) TF_ROUND(16) TF_ROUND(24)
    x0 += K1; x1 += K2 + 4u;
    TF_ROUND(13) TF_ROUND(15) TF_ROUND(26) TF_ROUND(6)
    x0 += K2; x1 += K0 + 5u;
#undef TF_ROUND
    return x0 ^ x1;
}

// Epilogue for one (b,i,j): writes ms/sample/entropy, counts sample into
// g_cnt (integer atomic -> deterministic), returns (entropy, lsm_term).
__device__ __forceinline__ float2 epi_one(int b, int i, int j, float logit,
                                          float* __restrict__ out) {
    float ms = (i == j) ? (logit - 1e8f) : logit;
    uint32_t f = ((uint32_t)b << 14) | ((uint32_t)i << 7) | (uint32_t)j;
    uint32_t bits = threefry_bits(f);
    float u = __uint_as_float((bits >> 9) | 0x3f800000u) - 1.0f;
    float p = 1.0f / (1.0f + expf(-ms));
    float c = log1pf(expf(-fabsf(ms)));          // shared softplus tail
    float sp_pos = fmaxf(ms, 0.0f) + c;          // softplus(ms)
    float sp_neg = fmaxf(-ms, 0.0f) + c;         // softplus(-ms)
    float ent = fmaf(p, sp_neg, (1.0f - p) * sp_pos);
    float s;
    if (u < p) { s = 1.0f; atomicAdd(&g_cnt[i * LL + j], 1); } else s = 0.0f;
    out[OFF_MS + f] = ms;
    out[OFF_S + f]  = s;
    out[OFF_E + f]  = ent;
    float lsm = sp_pos - ms * s;
    return make_float2(ent, lsm);
}

// ---------------------------------------------------------------------------
// Pairwise core, PERSISTENT: 592 blocks x 128 thr @ occ 4 = exactly resident.
// 1024 tiles of 16(i) x 16(j); tile t: b=t>>6, it=(t>>3)&7, jt=t&7.
// Full D=256 in smem per tile (no d-chunking). 2 elements/thread.
// Worst SM carries 7 tiles vs 6.92 avg -> ~8% over the 15.9us MUFU floor.
// ---------------------------------------------------------------------------
#define PW2_STR 260

__global__ __launch_bounds__(128, 4)
void pairwise_kernel(const float* __restrict__ Uv,
                     const float* __restrict__ biasp,
                     float* __restrict__ out) {
    __shared__ __align__(16) float sl[16 * PW2_STR];
    __shared__ __align__(16) float sr[16 * PW2_STR];
    __shared__ __align__(16) float su[256];
    __shared__ float rshare[2][4];
    const int tid = threadIdx.x;
    const int tx = tid & 7, ty = tid >> 3;    // j-base (0..7), i (0..15)
    su[tid] = Uv[tid];
    su[tid + 128] = Uv[tid + 128];
    const float bias = __ldg(biasp);

    for (int t = blockIdx.x; t < 1024; t += 592) {
        const int b = t >> 6, it = (t >> 3) & 7, jt = t & 7;
        const int ibase = it * 16, jbase = jt * 16;
        __syncthreads();   // protect smem reuse across tiles
        // load 16 l-rows + 16 r-rows x 256 floats (64 float4 each)
        for (int idx = tid; idx < 32 * 64; idx += 128) {
            int rr = idx >> 6, cc = (idx & 63) * 4;
            if (rr < 16) {
                *(float4*)&sl[rr * PW2_STR + cc] =
                    *(const float4*)&g_el[(b * 128 + ibase + rr) * 256 + cc];
            } else {
                *(float4*)&sr[(rr - 16) * PW2_STR + cc] =
                    *(const float4*)&g_er[(b * 128 + jbase + (rr - 16)) * 256 + cc];
            }
        }
        __syncthreads();

        const float* pl  = sl + ty * PW2_STR;
        const float* pr0 = sr + tx * PW2_STR;
        const float* pr1 = sr + (tx + 8) * PW2_STR;
        float a0 = 0.0f, a1 = 0.0f;
#pragma unroll 4
        for (int d = 0; d < 256; d += 4) {
            float4 L  = *(const float4*)(pl + d);
            float4 R0 = *(const float4*)(pr0 + d);
            float4 R1 = *(const float4*)(pr1 + d);
            float4 U  = *(const float4*)(su + d);
            a0 = fmaf(U.x, rcpf(fmaf(L.x, R0.x, 1.0f)) - 0.5f, a0);
            a1 = fmaf(U.x, rcpf(fmaf(L.x, R1.x, 1.0f)) - 0.5f, a1);
            a0 = fmaf(U.y, rcpf(fmaf(L.y, R0.y, 1.0f)) - 0.5f, a0);
            a1 = fmaf(U.y, rcpf(fmaf(L.y, R1.y, 1.0f)) - 0.5f, a1);
            a0 = fmaf(U.z, rcpf(fmaf(L.z, R0.z, 1.0f)) - 0.5f, a0);
            a1 = fmaf(U.z, rcpf(fmaf(L.z, R1.z, 1.0f)) - 0.5f, a1);
            a0 = fmaf(U.w, rcpf(fmaf(L.w, R0.w, 1.0f)) - 0.5f, a0);
            a1 = fmaf(U.w, rcpf(fmaf(L.w, R1.w, 1.0f)) - 0.5f, a1);
        }

        float2 e0 = epi_one(b, ibase + ty, jbase + tx,
                            fmaf(-2.0f, a0, bias), out);
        float2 e1 = epi_one(b, ibase + ty, jbase + tx + 8,
                            fmaf(-2.0f, a1, bias), out);

        // per-tile block reduce (shfl tree + 4-warp combine), deterministic
        float ent = e0.x + e1.x, lsm = e0.y + e1.y;
#pragma unroll
        for (int o = 16; o > 0; o >>= 1) {
            ent += __shfl_xor_sync(0xffffffffu, ent, o);
            lsm += __shfl_xor_sync(0xffffffffu, lsm, o);
        }
        const int wid = tid >> 5;
        if ((tid & 31) == 0) { rshare[0][wid] = ent; rshare[1][wid] = lsm; }
        __syncthreads();
        if (tid == 0) {
            float se = 0.0f, sm = 0.0f;
#pragma unroll
            for (int ww = 0; ww < 4; ww++) { se += rshare[0][ww]; sm += rshare[1][ww]; }
            g_ent_part[t] = se;
            g_lsm_part[t] = sm;
        }
    }
}

// ---------------------------------------------------------------------------
// Tail: blocks 0-63 convert+reset graph_batch counts; block 64 finishes
// entropy_regularization (16 per-batch sums of 64 tile partials, fixed order)
// and the log_softmax scalar (one warp reduces 1024 partials).
// ---------------------------------------------------------------------------
__global__ void tail_kernel(float* __restrict__ out) {
    const int bidx = blockIdx.x;
    if (bidx < 64) {
        int idx = bidx * 256 + threadIdx.x;   // 0..16383
        out[OFF_GB + idx] = (float)g_cnt[idx] * 0.0625f;
        g_cnt[idx] = 0;                        // reset for next graph replay
    } else {
        int t = threadIdx.x;
        if (t < 16) {
            float s = 0.0f;
#pragma unroll
            for (int k = 0; k < 64; k++) s += g_ent_part[t * 64 + k];
            out[OFF_ER + t] = s * (1.0f / 16384.0f);
        }
        if (t >= 32 && t < 64) {
            int lane = t - 32;
            float s = 0.0f;
#pragma unroll
            for (int k = 0; k < 32; k++) s += g_lsm_part[lane * 32 + k];
#pragma unroll
            for (int o = 16; o > 0; o >>= 1)
                s += __shfl_xor_sync(0xffffffffu, s, o);
            if (lane == 0) out[OFF_LSM] = s * (1.0f / (float)NEL);
        }
    }
}

// ---------------------------------------------------------------------------
extern "C" void kernel_launch(void* const* d_in, const int* in_sizes, int n_in,
                              void* d_out, int out_size) {
    (void)in_sizes; (void)n_in; (void)out_size;
    const float* enc  = (const float*)d_in[0]; // (16,128,256)
    const float* W_l  = (const float*)d_in[1]; // (256,256)
    const float* W_r  = (const float*)d_in[2]; // (256,256)
    const float* U    = (const float*)d_in[3]; // (256,)
    const float* bias = (const float*)d_in[4]; // (1,)
    float* out = (float*)d_out;

    split_kernel<<<640, 256>>>(enc, W_l, W_r);
    gemm_tc_kernel<<<dim3(4, 32, 2), 256>>>();
    pairwise_kernel<<<592, 128>>>(U, bias, out);
    tail_kernel<<<65, 256>>>(out);
}